// round 8
// baseline (speedup 1.0000x reference)
#include <cuda_runtime.h>
#include <math.h>

#define N_ 8
#define C_ 512
#define H_ 64
#define W_ 64

typedef unsigned long long ull;

__device__ __forceinline__ ull pack2(float lo, float hi) {
    ull r; asm("mov.b64 %0, {%1, %2};" : "=l"(r) : "f"(lo), "f"(hi)); return r;
}
__device__ __forceinline__ void unpack2(ull v, float& lo, float& hi) {
    asm("mov.b64 {%0, %1}, %2;" : "=f"(lo), "=f"(hi) : "l"(v));
}
__device__ __forceinline__ ull fma2(ull a, ull b, ull c) {
    ull d; asm("fma.rn.f32x2 %0, %1, %2, %3;" : "=l"(d) : "l"(a), "l"(b), "l"(c)); return d;
}
__device__ __forceinline__ ull mul2(ull a, ull b) {
    ull d; asm("mul.rn.f32x2 %0, %1, %2;" : "=l"(d) : "l"(a), "l"(b)); return d;
}
__device__ __forceinline__ float tanh_ap(float x) {
    float r; asm("tanh.approx.f32 %0, %1;" : "=f"(r) : "f"(x)); return r;
}
// tanh-form GELU on an f32x2 pair
__device__ __forceinline__ ull gelu2(ull y, ull C1, ull C0, ull HF) {
    ull x2 = mul2(y, y);
    ull u  = mul2(y, fma2(C1, x2, C0));
    float u0, u1;
    unpack2(u, u0, u1);
    ull t2 = pack2(tanh_ap(u0), tanh_ap(u1));
    ull r  = fma2(t2, HF, HF);
    return mul2(y, r);
}

// off_w transposed to [c][o]; dw_w padded to stride 12
__device__ float g_offw_t[C_ * 32];
__device__ __align__(16) float g_dww_p[C_ * 12];

__global__ void prep_kernel(const float* __restrict__ off_w,
                            const float* __restrict__ dw_w) {
    int i = blockIdx.x * 1024 + threadIdx.x;   // 16 x 1024 = 16384
    int o = i >> 9;
    int c = i & 511;
    g_offw_t[c * 32 + o] = off_w[i];
    if (i < C_ * 12) {
        int cc = i / 12;
        int k  = i - cc * 12;
        g_dww_p[i] = (k < 9) ? dw_w[cc * 9 + k] : 0.0f;
    }
}

// Shared memory per CTA (256 threads, 16 pixels):
//   region0 : 8704  (x1 [512][16] A-D; offs [0:512] reduce->E0; stage [512][17] E/F)
//   offsP   : 4608  (A/B: psum/psq stride-17; D: 8 partial tiles [8][32][16];
//                    E0/E: spw 4x256 ull + spo 256 int4)
//   mu,rs   : 32
// total = 13344 floats = 53376 bytes -> 4 CTAs/SM
#define SMEM_FLOATS (8704 + 4608 + 32)

__global__ __launch_bounds__(256, 4)
void das_fused_kernel(const float* __restrict__ in0,   // input_first NCHW
                      const float* __restrict__ inL,   // input_last  NHWC
                      const float* __restrict__ dw_b,  // [C]
                      const float* __restrict__ ln_g,  // [C]
                      const float* __restrict__ ln_b,  // [C]
                      const float* __restrict__ off_b, // [2G]
                      float* __restrict__ out)         // NCHW
{
    extern __shared__ float sm[];
    float* x1    = sm;                 // stride 16 rows (A-D)
    float* stage = sm;                 // stride 17 rows (E-F)
    float* offs  = sm;                 // [0:512] after reduce (x1 dead)
    float* offsP = sm + 8704;          // 4608
    float* psum  = offsP;              // 8 x 17 = 136 (stride 17)
    float* psq   = offsP + 136;        // 8 x 17 = 136
    ull*   spw   = (ull*)offsP;        // 4 x 256 ull (E0/E)
    int4*  spo   = (int4*)(offsP + 2048);  // 256 int4 (E0/E)
    float* mu    = sm + 8704 + 4608;   // 16
    float* rs    = mu + 16;            // 16

    const int t       = threadIdx.x;
    const int quarter = blockIdx.x;    // 0..3
    const int h       = blockIdx.y;
    const int n       = blockIdx.z;
    const int wbase   = quarter * 16;

    const int w4   = t & 3;            // w-quad within the 16 pixels
    const int cgrp = t >> 2;           // 0..63, 8 channels each
    const int lane = t & 31;

    // ======== Phase A: depthwise 3x3 conv + bias + LN partials ==============
    float s0 = 0.f, s1 = 0.f, s2 = 0.f, s3 = 0.f;
    float q0 = 0.f, q1 = 0.f, q2 = 0.f, q3 = 0.f;

    const float* in_n = in0 + (size_t)n * C_ * H_ * W_;

    #pragma unroll 4
    for (int i = 0; i < 8; ++i) {
        int c = cgrp * 8 + i;
        const float4* wp4 = (const float4*)(g_dww_p + c * 12);
        float4 wA = wp4[0];
        float4 wB = wp4[1];
        float4 wC = wp4[2];
        const float* cp = in_n + (size_t)c * H_ * W_;
        float b = dw_b[c];
        float a0 = b, a1 = b, a2 = b, a3 = b;
        #pragma unroll
        for (int dy = -1; dy <= 1; ++dy) {
            int hy = h + dy;
            if ((unsigned)hy < (unsigned)H_) {          // uniform across block
                const float* r = cp + hy * W_ + wbase + w4 * 4;
                float4 v = *(const float4*)r;
                float lf = __shfl_up_sync(0xffffffffu, v.w, 1, 4);
                if (w4 == 0) lf = (wbase > 0) ? r[-1] : 0.f;
                float rt = __shfl_down_sync(0xffffffffu, v.x, 1, 4);
                if (w4 == 3) rt = (wbase + 16 < W_) ? r[4] : 0.f;
                float k0, k1, k2;
                if (dy == -1)     { k0 = wA.x; k1 = wA.y; k2 = wA.z; }
                else if (dy == 0) { k0 = wA.w; k1 = wB.x; k2 = wB.y; }
                else              { k0 = wB.z; k1 = wB.w; k2 = wC.x; }
                a0 += k0 * lf  + k1 * v.x + k2 * v.y;
                a1 += k0 * v.x + k1 * v.y + k2 * v.z;
                a2 += k0 * v.y + k1 * v.z + k2 * v.w;
                a3 += k0 * v.z + k1 * v.w + k2 * rt;
            }
        }
        s0 += a0; q0 += a0 * a0;
        s1 += a1; q1 += a1 * a1;
        s2 += a2; q2 += a2 * a2;
        s3 += a3; q3 += a3 * a3;
        *(float4*)(x1 + c * 16 + w4 * 4) = make_float4(a0, a1, a2, a3);
    }

    // combine the 8 channel-subgroups sharing each w4 within the warp
    #pragma unroll
    for (int d = 4; d <= 16; d <<= 1) {
        s0 += __shfl_xor_sync(0xffffffffu, s0, d);
        s1 += __shfl_xor_sync(0xffffffffu, s1, d);
        s2 += __shfl_xor_sync(0xffffffffu, s2, d);
        s3 += __shfl_xor_sync(0xffffffffu, s3, d);
        q0 += __shfl_xor_sync(0xffffffffu, q0, d);
        q1 += __shfl_xor_sync(0xffffffffu, q1, d);
        q2 += __shfl_xor_sync(0xffffffffu, q2, d);
        q3 += __shfl_xor_sync(0xffffffffu, q3, d);
    }
    {
        int warpId = t >> 5;               // 0..7; covers 64 channels
        if (lane < 4) {                    // lane == w4
            psum[warpId * 17 + lane * 4 + 0] = s0;
            psum[warpId * 17 + lane * 4 + 1] = s1;
            psum[warpId * 17 + lane * 4 + 2] = s2;
            psum[warpId * 17 + lane * 4 + 3] = s3;
            psq [warpId * 17 + lane * 4 + 0] = q0;
            psq [warpId * 17 + lane * 4 + 1] = q1;
            psq [warpId * 17 + lane * 4 + 2] = q2;
            psq [warpId * 17 + lane * 4 + 3] = q3;
        }
    }
    __syncthreads();

    // ======== Phase B: finish LN statistics (16 pixels x 8 partials) ========
    if (t < 128) {
        int px = t >> 3;      // 0..15
        int j  = t & 7;       // partial (warp) index
        float s = psum[j * 17 + px];
        float q = psq [j * 17 + px];
        #pragma unroll
        for (int d = 4; d >= 1; d >>= 1) {
            s += __shfl_xor_sync(0xffffffffu, s, d);
            q += __shfl_xor_sync(0xffffffffu, q, d);
        }
        if (j == 0) {
            float m = s * (1.0f / 512.0f);
            float var = q * (1.0f / 512.0f) - m * m;
            mu[px] = m;
            rs[px] = rsqrtf(var + 1e-6f);
        }
    }
    __syncthreads();

    // ======== Phase C: LN + fast GELU, f32x2, in place =======================
    {
        float4 m4 = *(const float4*)(mu + w4 * 4);
        float4 r4 = *(const float4*)(rs + w4 * 4);
        const ull C1 = pack2(0.0356774081f, 0.0356774081f);
        const ull C0 = pack2(0.7978845608f, 0.7978845608f);
        const ull HF = pack2(0.5f, 0.5f);
        ull r2lo = pack2(r4.x, r4.y);
        ull r2hi = pack2(r4.z, r4.w);
        ull mn2lo = pack2(-m4.x, -m4.y);
        ull mn2hi = pack2(-m4.z, -m4.w);
        #pragma unroll
        for (int q = 0; q < 2; ++q) {
            int c0 = cgrp * 8 + q * 4;
            float4 gq = *(const float4*)(ln_g + c0);
            float4 bq = *(const float4*)(ln_b + c0);
            float gga[4] = {gq.x, gq.y, gq.z, gq.w};
            float bba[4] = {bq.x, bq.y, bq.z, bq.w};
            #pragma unroll
            for (int j = 0; j < 4; ++j) {
                int c = c0 + j;
                ull g2 = pack2(gga[j], gga[j]);
                ull b2 = pack2(bba[j], bba[j]);
                ulonglong2 yv = *(const ulonglong2*)(x1 + c * 16 + w4 * 4);
                ull Alo = mul2(r2lo, g2);
                ull Blo = fma2(mn2lo, Alo, b2);
                ull Ahi = mul2(r2hi, g2);
                ull Bhi = fma2(mn2hi, Ahi, b2);
                yv.x = fma2(yv.x, Alo, Blo);
                yv.y = fma2(yv.y, Ahi, Bhi);
                yv.x = gelu2(yv.x, C1, C0, HF);
                yv.y = gelu2(yv.y, C1, C0, HF);
                *(ulonglong2*)(x1 + c * 16 + w4 * 4) = yv;
            }
        }
    }
    __syncthreads();

    // ======== Phase D: offset projection, 4o x 4w tiles, f32x2 ==============
    {
        const int g4   = t & 3;          // w-quad
        const int og   = (t >> 2) & 7;   // o-quad
        const int part = t >> 5;         // 0..7, 64 channels each (warp-uniform)
        const float4* wt = (const float4*)g_offw_t;    // [c*8 + og]
        ull a00 = 0, a01 = 0, a10 = 0, a11 = 0;
        ull a20 = 0, a21 = 0, a30 = 0, a31 = 0;
        int cb = part * 64;
        #pragma unroll 4
        for (int ci = 0; ci < 64; ++ci) {
            int c = cb + ci;
            ulonglong2 xv = *(const ulonglong2*)(x1 + c * 16 + g4 * 4);
            float4 wv = __ldg(wt + c * 8 + og);
            ull w0 = pack2(wv.x, wv.x);
            ull w1 = pack2(wv.y, wv.y);
            ull w2 = pack2(wv.z, wv.z);
            ull w3 = pack2(wv.w, wv.w);
            a00 = fma2(w0, xv.x, a00); a01 = fma2(w0, xv.y, a01);
            a10 = fma2(w1, xv.x, a10); a11 = fma2(w1, xv.y, a11);
            a20 = fma2(w2, xv.x, a20); a21 = fma2(w2, xv.y, a21);
            a30 = fma2(w3, xv.x, a30); a31 = fma2(w3, xv.y, a31);
        }
        float* pp = offsP + part * 512 + (og * 4) * 16 + g4 * 4;
        ((ull*)(pp +  0))[0] = a00; ((ull*)(pp +  0))[1] = a01;
        ((ull*)(pp + 16))[0] = a10; ((ull*)(pp + 16))[1] = a11;
        ((ull*)(pp + 32))[0] = a20; ((ull*)(pp + 32))[1] = a21;
        ((ull*)(pp + 48))[0] = a30; ((ull*)(pp + 48))[1] = a31;
    }
    __syncthreads();

    // reduce 8 partials -> offs (in dead x1 region), add bias
    {
        #pragma unroll
        for (int r = 0; r < 2; ++r) {
            int idx = t + r * 256;             // o*16 + w
            int o = idx >> 4;
            float s = offsP[idx];
            #pragma unroll
            for (int p = 1; p < 8; ++p) s += offsP[p * 512 + idx];
            offs[idx] = s + __ldg(off_b + o);
        }
    }
    __syncthreads();

    // ======== Phase E0: per-sample bilinear params, pre-packed ==============
    {
        const int S = t;            // 0..255
        const int g = S >> 4;
        const int w = S & 15;
        float px = (float)(wbase + w) + offs[(2 * g + 0) * 16 + w];
        float py = (float)h           + offs[(2 * g + 1) * 16 + w];
        float x0f = floorf(px);
        float y0f = floorf(py);
        float fx = px - x0f;
        float fy = py - y0f;
        int x0 = (int)x0f;
        int y0 = (int)y0f;
        float vx0 = (x0f >= 0.f       && x0f <= 63.f)       ? 1.f : 0.f;
        float vx1 = (x0f + 1.f >= 0.f && x0f + 1.f <= 63.f) ? 1.f : 0.f;
        float vy0 = (y0f >= 0.f       && y0f <= 63.f)       ? 1.f : 0.f;
        float vy1 = (y0f + 1.f >= 0.f && y0f + 1.f <= 63.f) ? 1.f : 0.f;
        int xc0 = min(max(x0, 0), 63);
        int xc1 = min(max(x0 + 1, 0), 63);
        int yc0 = min(max(y0, 0), 63);
        int yc1 = min(max(y0 + 1, 0), 63);
        float w00 = (1.f - fx) * (1.f - fy) * vx0 * vy0;
        float w10 = fx * (1.f - fy) * vx1 * vy0;
        float w01 = (1.f - fx) * fy * vx0 * vy1;
        float w11 = fx * fy * vx1 * vy1;
        spw[S +   0] = pack2(w00, w00);
        spw[S + 256] = pack2(w10, w10);
        spw[S + 512] = pack2(w01, w01);
        spw[S + 768] = pack2(w11, w11);
        spo[S] = make_int4((yc0 * 64 + xc0) * 512, (yc0 * 64 + xc1) * 512,
                           (yc1 * 64 + xc0) * 512, (yc1 * 64 + xc1) * 512);
    }
    __syncthreads();

    // ======== Phase E: coalesced bilinear gather (8 lanes per sample) =======
    {
        const int wp = t >> 5;        // warp 0..7
        const int s  = (t >> 3) & 3;  // sample within warp
        const int e  = t & 7;         // quad within GC=32
        const float* inL_n = inL + (size_t)n * H_ * W_ * C_;
        #pragma unroll
        for (int k = 0; k < 8; ++k) {
            int S = k * 32 + wp * 4 + s;    // 0..255
            int g = S >> 4;
            int w = S & 15;
            ull w00 = spw[S];
            ull w10 = spw[S + 256];
            ull w01 = spw[S + 512];
            ull w11 = spw[S + 768];
            int4 ofs = spo[S];
            const float* bp = inL_n + g * 32 + e * 4;
            ulonglong2 a = *(const ulonglong2*)(bp + ofs.x);
            ulonglong2 b = *(const ulonglong2*)(bp + ofs.y);
            ulonglong2 c = *(const ulonglong2*)(bp + ofs.z);
            ulonglong2 d = *(const ulonglong2*)(bp + ofs.w);
            ull rlo = mul2(w00, a.x);
            rlo = fma2(w10, b.x, rlo);
            rlo = fma2(w01, c.x, rlo);
            rlo = fma2(w11, d.x, rlo);
            ull rhi = mul2(w00, a.y);
            rhi = fma2(w10, b.y, rhi);
            rhi = fma2(w01, c.y, rhi);
            rhi = fma2(w11, d.y, rhi);
            float r0, r1, r2, r3;
            unpack2(rlo, r0, r1);
            unpack2(rhi, r2, r3);
            int crow = g * 32 + e * 4;
            // stride-17 rows: bank = (4e + 17j + w) % 32 -> conflict-free
            stage[(crow + 0) * 17 + w] = r0;
            stage[(crow + 1) * 17 + w] = r1;
            stage[(crow + 2) * 17 + w] = r2;
            stage[(crow + 3) * 17 + w] = r3;
        }
    }
    __syncthreads();

    // ======== Phase F: coalesced copy-out ====================================
    {
        float* outp = out + (size_t)n * C_ * H_ * W_ + (size_t)h * W_ + wbase;
        #pragma unroll
        for (int k = 0; k < 8; ++k) {
            int c = (t >> 2) + k * 64;
            float4 r;
            r.x = stage[c * 17 + w4 * 4 + 0];
            r.y = stage[c * 17 + w4 * 4 + 1];
            r.z = stage[c * 17 + w4 * 4 + 2];
            r.w = stage[c * 17 + w4 * 4 + 3];
            *(float4*)(outp + (size_t)c * (H_ * W_) + w4 * 4) = r;
        }
    }
}

extern "C" void kernel_launch(void* const* d_in, const int* in_sizes, int n_in,
                              void* d_out, int out_size)
{
    (void)in_sizes; (void)n_in; (void)out_size;
    const float* in0   = (const float*)d_in[0];
    const float* inL   = (const float*)d_in[1];
    const float* dw_w  = (const float*)d_in[2];
    const float* dw_b  = (const float*)d_in[3];
    const float* ln_g  = (const float*)d_in[4];
    const float* ln_b  = (const float*)d_in[5];
    const float* off_w = (const float*)d_in[6];
    const float* off_b = (const float*)d_in[7];
    float* out = (float*)d_out;

    prep_kernel<<<16, 1024>>>(off_w, dw_w);

    const int smem_bytes = SMEM_FLOATS * sizeof(float);   // 53376
    cudaFuncSetAttribute(das_fused_kernel,
                         cudaFuncAttributeMaxDynamicSharedMemorySize, smem_bytes);

    dim3 grid(4, H_, N_);
    das_fused_kernel<<<grid, 256, smem_bytes>>>(in0, inL, dw_b,
                                                ln_g, ln_b, off_b, out);
}

// round 9
// speedup vs baseline: 1.1482x; 1.1482x over previous
#include <cuda_runtime.h>
#include <math.h>

#define N_ 8
#define C_ 512
#define H_ 64
#define W_ 64

typedef unsigned long long ull;

__device__ __forceinline__ ull pack2(float lo, float hi) {
    ull r; asm("mov.b64 %0, {%1, %2};" : "=l"(r) : "f"(lo), "f"(hi)); return r;
}
__device__ __forceinline__ void unpack2(ull v, float& lo, float& hi) {
    asm("mov.b64 {%0, %1}, %2;" : "=f"(lo), "=f"(hi) : "l"(v));
}
__device__ __forceinline__ ull fma2(ull a, ull b, ull c) {
    ull d; asm("fma.rn.f32x2 %0, %1, %2, %3;" : "=l"(d) : "l"(a), "l"(b), "l"(c)); return d;
}
__device__ __forceinline__ ull mul2(ull a, ull b) {
    ull d; asm("mul.rn.f32x2 %0, %1, %2;" : "=l"(d) : "l"(a), "l"(b)); return d;
}
__device__ __forceinline__ float tanh_ap(float x) {
    float r; asm("tanh.approx.f32 %0, %1;" : "=f"(r) : "f"(x)); return r;
}
// tanh-form GELU on an f32x2 pair
__device__ __forceinline__ ull gelu2(ull y, ull C1, ull C0, ull HF) {
    ull x2 = mul2(y, y);
    ull u  = mul2(y, fma2(C1, x2, C0));
    float u0, u1;
    unpack2(u, u0, u1);
    ull t2 = pack2(tanh_ap(u0), tanh_ap(u1));
    ull r  = fma2(t2, HF, HF);
    return mul2(y, r);
}

// off_w transposed to [c][o]; dw_w padded to stride 12
__device__ float g_offw_t[C_ * 32];
__device__ __align__(16) float g_dww_p[C_ * 12];

__global__ void prep_kernel(const float* __restrict__ off_w,
                            const float* __restrict__ dw_w) {
    int i = blockIdx.x * 1024 + threadIdx.x;   // 16 x 1024 = 16384
    int o = i >> 9;
    int c = i & 511;
    g_offw_t[c * 32 + o] = off_w[i];
    if (i < C_ * 12) {
        int cc = i / 12;
        int k  = i - cc * 12;
        g_dww_p[i] = (k < 9) ? dw_w[cc * 9 + k] : 0.0f;
    }
}

// Shared memory (floats), per CTA of 512 threads covering 32 pixels:
//   region0 (16896): x1 [512][32] A-D; after D: partials [0:8192],
//                    offs [8192:9216]; stage [512][33] E/F
//   offsP   (8192):  start-B: dww staged [0:6144], psum/psq [6144:7200]
//                    C-D: even-channel off_w [0:8192]
//                    E0/E: spw 4x512 ull [0:4096] + spo 512 int4 [4096:6144]
//   mu,rs   : 64
#define SMEM_FLOATS (16896 + 8192 + 64)

__global__ __launch_bounds__(512, 2)
void das_fused_kernel(const float* __restrict__ in0,   // input_first NCHW
                      const float* __restrict__ inL,   // input_last  NHWC
                      const float* __restrict__ dw_b,  // [C]
                      const float* __restrict__ ln_g,  // [C]
                      const float* __restrict__ ln_b,  // [C]
                      const float* __restrict__ off_b, // [2G]
                      float* __restrict__ out)         // NCHW
{
    extern __shared__ float sm[];
    float* x1    = sm;                 // stride 32 rows (A-D)
    float* stage = sm;                 // stride 33 rows (E-F)
    float* parts = sm;                 // [0:8192] after D (x1 dead)
    float* offs  = sm + 8192;          // [8192:9216] after reduce
    float* offsP = sm + 16896;         // 8192
    float* dwws  = offsP;              // [0:6144] staged dw weights
    float* psum  = offsP + 6144;       // 16 x 33 = 528
    float* psq   = offsP + 6672;       // 16 x 33 = 528
    float* evenW = offsP;              // [0:8192] staged even off_w (C-D)
    ull*   spw   = (ull*)offsP;        // [0:4096] (E0/E)
    int4*  spo   = (int4*)(offsP + 4096);  // [4096:6144] (E0/E)
    float* mu    = sm + 16896 + 8192;  // 32
    float* rs    = mu + 32;            // 32

    const int t     = threadIdx.x;
    const int half  = blockIdx.x;      // 0 or 1
    const int h     = blockIdx.y;
    const int n     = blockIdx.z;
    const int wbase = half * 32;

    const int w4   = t & 7;            // w-quad within the 32 pixels
    const int cgrp = t >> 3;           // 0..63, 8 channels each
    const int lane = t & 31;

    // ======== Phase 0: stage depthwise weights into smem =====================
    {
        const float4* s4 = (const float4*)g_dww_p;
        float4* d4 = (float4*)dwws;
        d4[t]        = s4[t];
        d4[t + 512]  = s4[t + 512];
        d4[t + 1024] = s4[t + 1024];
    }
    __syncthreads();

    // ======== Phase A: depthwise 3x3 conv + bias + LN partials ==============
    float s0 = 0.f, s1 = 0.f, s2 = 0.f, s3 = 0.f;
    float q0 = 0.f, q1 = 0.f, q2 = 0.f, q3 = 0.f;

    const float* in_n = in0 + (size_t)n * C_ * H_ * W_;

    #pragma unroll 4
    for (int i = 0; i < 8; ++i) {
        int c = cgrp * 8 + i;
        const float4* wp4 = (const float4*)(dwws + c * 12);
        float4 wA = wp4[0];
        float4 wB = wp4[1];
        float4 wC = wp4[2];
        const float* cp = in_n + (size_t)c * H_ * W_;
        float b = dw_b[c];
        float a0 = b, a1 = b, a2 = b, a3 = b;
        #pragma unroll
        for (int dy = -1; dy <= 1; ++dy) {
            int hy = h + dy;
            if ((unsigned)hy < (unsigned)H_) {          // uniform across block
                const float* r = cp + hy * W_ + wbase + w4 * 4;
                float4 v = *(const float4*)r;
                float lf = __shfl_up_sync(0xffffffffu, v.w, 1, 8);
                if (w4 == 0) lf = (wbase > 0) ? r[-1] : 0.f;
                float rt = __shfl_down_sync(0xffffffffu, v.x, 1, 8);
                if (w4 == 7) rt = (wbase + 32 < W_) ? r[4] : 0.f;
                float k0, k1, k2;
                if (dy == -1)     { k0 = wA.x; k1 = wA.y; k2 = wA.z; }
                else if (dy == 0) { k0 = wA.w; k1 = wB.x; k2 = wB.y; }
                else              { k0 = wB.z; k1 = wB.w; k2 = wC.x; }
                a0 += k0 * lf  + k1 * v.x + k2 * v.y;
                a1 += k0 * v.x + k1 * v.y + k2 * v.z;
                a2 += k0 * v.y + k1 * v.z + k2 * v.w;
                a3 += k0 * v.z + k1 * v.w + k2 * rt;
            }
        }
        s0 += a0; q0 += a0 * a0;
        s1 += a1; q1 += a1 * a1;
        s2 += a2; q2 += a2 * a2;
        s3 += a3; q3 += a3 * a3;
        *(float4*)(x1 + c * 32 + w4 * 4) = make_float4(a0, a1, a2, a3);
    }

    s0 += __shfl_xor_sync(0xffffffffu, s0, 8);
    s0 += __shfl_xor_sync(0xffffffffu, s0, 16);
    s1 += __shfl_xor_sync(0xffffffffu, s1, 8);
    s1 += __shfl_xor_sync(0xffffffffu, s1, 16);
    s2 += __shfl_xor_sync(0xffffffffu, s2, 8);
    s2 += __shfl_xor_sync(0xffffffffu, s2, 16);
    s3 += __shfl_xor_sync(0xffffffffu, s3, 8);
    s3 += __shfl_xor_sync(0xffffffffu, s3, 16);
    q0 += __shfl_xor_sync(0xffffffffu, q0, 8);
    q0 += __shfl_xor_sync(0xffffffffu, q0, 16);
    q1 += __shfl_xor_sync(0xffffffffu, q1, 8);
    q1 += __shfl_xor_sync(0xffffffffu, q1, 16);
    q2 += __shfl_xor_sync(0xffffffffu, q2, 8);
    q2 += __shfl_xor_sync(0xffffffffu, q2, 16);
    q3 += __shfl_xor_sync(0xffffffffu, q3, 8);
    q3 += __shfl_xor_sync(0xffffffffu, q3, 16);
    {
        int warpId = t >> 5;               // 0..15
        if (lane < 8) {
            psum[warpId * 33 + lane * 4 + 0] = s0;
            psum[warpId * 33 + lane * 4 + 1] = s1;
            psum[warpId * 33 + lane * 4 + 2] = s2;
            psum[warpId * 33 + lane * 4 + 3] = s3;
            psq [warpId * 33 + lane * 4 + 0] = q0;
            psq [warpId * 33 + lane * 4 + 1] = q1;
            psq [warpId * 33 + lane * 4 + 2] = q2;
            psq [warpId * 33 + lane * 4 + 3] = q3;
        }
    }
    __syncthreads();

    // ======== Phase B: finish LN statistics, all threads + shfl =============
    {
        int px = t >> 4;      // 0..31
        int j  = t & 15;      // partial index
        float s = psum[j * 33 + px];
        float q = psq [j * 33 + px];
        #pragma unroll
        for (int d = 8; d >= 1; d >>= 1) {
            s += __shfl_xor_sync(0xffffffffu, s, d);
            q += __shfl_xor_sync(0xffffffffu, q, d);
        }
        if (j == 0) {
            float m = s * (1.0f / 512.0f);
            float var = q * (1.0f / 512.0f) - m * m;
            mu[px] = m;
            rs[px] = rsqrtf(var + 1e-6f);
        }
    }
    __syncthreads();

    // ======== Phase C: LN + fast GELU, f32x2, in place =======================
    // Also: stage even-channel off_w into evenW (psum/psq now dead).
    {
        // thread t stages half a row of even channel 2*(t>>1)
        int ec = t >> 1;
        int hr = t & 1;
        const float4* srcw = (const float4*)(g_offw_t + (ec * 2) * 32 + hr * 16);
        float4* dstw = (float4*)(evenW + ec * 32 + hr * 16);
        dstw[0] = srcw[0];
        dstw[1] = srcw[1];
        dstw[2] = srcw[2];
        dstw[3] = srcw[3];

        float4 m4 = *(const float4*)(mu + w4 * 4);
        float4 r4 = *(const float4*)(rs + w4 * 4);
        const ull C1 = pack2(0.0356774081f, 0.0356774081f);
        const ull C0 = pack2(0.7978845608f, 0.7978845608f);
        const ull HF = pack2(0.5f, 0.5f);
        ull r2lo = pack2(r4.x, r4.y);
        ull r2hi = pack2(r4.z, r4.w);
        ull mn2lo = pack2(-m4.x, -m4.y);
        ull mn2hi = pack2(-m4.z, -m4.w);
        #pragma unroll
        for (int q = 0; q < 2; ++q) {
            int c0 = cgrp * 8 + q * 4;
            float4 gq = *(const float4*)(ln_g + c0);
            float4 bq = *(const float4*)(ln_b + c0);
            float gga[4] = {gq.x, gq.y, gq.z, gq.w};
            float bba[4] = {bq.x, bq.y, bq.z, bq.w};
            #pragma unroll
            for (int j = 0; j < 4; ++j) {
                int c = c0 + j;
                ull g2 = pack2(gga[j], gga[j]);
                ull b2 = pack2(bba[j], bba[j]);
                ulonglong2 yv = *(const ulonglong2*)(x1 + c * 32 + w4 * 4);
                ull Alo = mul2(r2lo, g2);
                ull Blo = fma2(mn2lo, Alo, b2);
                ull Ahi = mul2(r2hi, g2);
                ull Bhi = fma2(mn2hi, Ahi, b2);
                yv.x = fma2(yv.x, Alo, Blo);
                yv.y = fma2(yv.y, Ahi, Bhi);
                yv.x = gelu2(yv.x, C1, C0, HF);
                yv.y = gelu2(yv.y, C1, C0, HF);
                *(ulonglong2*)(x1 + c * 32 + w4 * 4) = yv;
            }
        }
    }
    __syncthreads();

    // ======== Phase D: offset projection; even c weights via smem ===========
    {
        const int g4   = t & 7;          // w-quad
        const int og   = (t >> 3) & 7;   // o-quad
        const int part = t >> 6;         // c-part, 64 channels each
        const float4* wt = (const float4*)g_offw_t;    // [c*8 + og] (odd c)
        ull a00 = 0, a01 = 0, a10 = 0, a11 = 0;
        ull a20 = 0, a21 = 0, a30 = 0, a31 = 0;
        int cb = part * 64;
        #pragma unroll 4
        for (int ci = 0; ci < 64; ++ci) {
            int c = cb + ci;
            ulonglong2 xv = *(const ulonglong2*)(x1 + c * 32 + g4 * 4);
            float4 wv;
            if ((ci & 1) == 0)
                wv = *(const float4*)(evenW + (c >> 1) * 32 + og * 4);
            else
                wv = __ldg(wt + c * 8 + og);
            ull w0 = pack2(wv.x, wv.x);
            ull w1 = pack2(wv.y, wv.y);
            ull w2 = pack2(wv.z, wv.z);
            ull w3 = pack2(wv.w, wv.w);
            a00 = fma2(w0, xv.x, a00); a01 = fma2(w0, xv.y, a01);
            a10 = fma2(w1, xv.x, a10); a11 = fma2(w1, xv.y, a11);
            a20 = fma2(w2, xv.x, a20); a21 = fma2(w2, xv.y, a21);
            a30 = fma2(w3, xv.x, a30); a31 = fma2(w3, xv.y, a31);
        }
        __syncthreads();   // all x1 + evenW reads complete
        float* pp = parts + part * 1024 + (og * 4) * 32 + g4 * 4;
        ((ull*)(pp +  0))[0] = a00; ((ull*)(pp +  0))[1] = a01;
        ((ull*)(pp + 32))[0] = a10; ((ull*)(pp + 32))[1] = a11;
        ((ull*)(pp + 64))[0] = a20; ((ull*)(pp + 64))[1] = a21;
        ((ull*)(pp + 96))[0] = a30; ((ull*)(pp + 96))[1] = a31;
    }
    __syncthreads();

    // reduce 8 partials -> offs, add bias
    {
        #pragma unroll
        for (int r = 0; r < 2; ++r) {
            int idx = t + r * 512;
            int o = idx >> 5;
            float s = parts[idx];
            #pragma unroll
            for (int p = 1; p < 8; ++p) s += parts[p * 1024 + idx];
            offs[idx] = s + __ldg(off_b + o);
        }
    }
    __syncthreads();

    // ======== Phase E0: per-sample bilinear params, pre-packed ==============
    {
        const int S = t;            // 0..511
        const int g = S >> 5;
        const int w = S & 31;
        float px = (float)(wbase + w) + offs[(2 * g + 0) * 32 + w];
        float py = (float)h           + offs[(2 * g + 1) * 32 + w];
        float x0f = floorf(px);
        float y0f = floorf(py);
        float fx = px - x0f;
        float fy = py - y0f;
        int x0 = (int)x0f;
        int y0 = (int)y0f;
        float vx0 = (x0f >= 0.f       && x0f <= 63.f)       ? 1.f : 0.f;
        float vx1 = (x0f + 1.f >= 0.f && x0f + 1.f <= 63.f) ? 1.f : 0.f;
        float vy0 = (y0f >= 0.f       && y0f <= 63.f)       ? 1.f : 0.f;
        float vy1 = (y0f + 1.f >= 0.f && y0f + 1.f <= 63.f) ? 1.f : 0.f;
        int xc0 = min(max(x0, 0), 63);
        int xc1 = min(max(x0 + 1, 0), 63);
        int yc0 = min(max(y0, 0), 63);
        int yc1 = min(max(y0 + 1, 0), 63);
        float w00 = (1.f - fx) * (1.f - fy) * vx0 * vy0;
        float w10 = fx * (1.f - fy) * vx1 * vy0;
        float w01 = (1.f - fx) * fy * vx0 * vy1;
        float w11 = fx * fy * vx1 * vy1;
        spw[S +    0] = pack2(w00, w00);
        spw[S +  512] = pack2(w10, w10);
        spw[S + 1024] = pack2(w01, w01);
        spw[S + 1536] = pack2(w11, w11);
        spo[S] = make_int4((yc0 * 64 + xc0) * 512, (yc0 * 64 + xc1) * 512,
                           (yc1 * 64 + xc0) * 512, (yc1 * 64 + xc1) * 512);
    }
    __syncthreads();

    // ======== Phase E: coalesced bilinear gather (8 lanes per sample) =======
    {
        const int wp = t >> 5;        // warp 0..15
        const int s  = (t >> 3) & 3;  // sample within warp
        const int e  = t & 7;         // quad within GC=32
        const float* inL_n = inL + (size_t)n * H_ * W_ * C_;
        #pragma unroll
        for (int k = 0; k < 8; ++k) {
            int S = k * 64 + wp * 4 + s;    // 0..511
            int g = S >> 5;
            int w = S & 31;
            ull w00 = spw[S];
            ull w10 = spw[S + 512];
            ull w01 = spw[S + 1024];
            ull w11 = spw[S + 1536];
            int4 ofs = spo[S];
            const float* bp = inL_n + g * 32 + e * 4;
            ulonglong2 a = *(const ulonglong2*)(bp + ofs.x);
            ulonglong2 b = *(const ulonglong2*)(bp + ofs.y);
            ulonglong2 c = *(const ulonglong2*)(bp + ofs.z);
            ulonglong2 d = *(const ulonglong2*)(bp + ofs.w);
            ull rlo = mul2(w00, a.x);
            rlo = fma2(w10, b.x, rlo);
            rlo = fma2(w01, c.x, rlo);
            rlo = fma2(w11, d.x, rlo);
            ull rhi = mul2(w00, a.y);
            rhi = fma2(w10, b.y, rhi);
            rhi = fma2(w01, c.y, rhi);
            rhi = fma2(w11, d.y, rhi);
            float r0, r1, r2, r3;
            unpack2(rlo, r0, r1);
            unpack2(rhi, r2, r3);
            int crow = g * 32 + e * 4;
            stage[(crow + 0) * 33 + w] = r0;
            stage[(crow + 1) * 33 + w] = r1;
            stage[(crow + 2) * 33 + w] = r2;
            stage[(crow + 3) * 33 + w] = r3;
        }
    }
    __syncthreads();

    // ======== Phase F: coalesced copy-out ====================================
    {
        float* outp = out + (size_t)n * C_ * H_ * W_ + (size_t)h * W_ + wbase;
        #pragma unroll
        for (int k = 0; k < 8; ++k) {
            int c = (t >> 3) + k * 64;
            float4 r;
            r.x = stage[c * 33 + w4 * 4 + 0];
            r.y = stage[c * 33 + w4 * 4 + 1];
            r.z = stage[c * 33 + w4 * 4 + 2];
            r.w = stage[c * 33 + w4 * 4 + 3];
            *(float4*)(outp + (size_t)c * (H_ * W_) + w4 * 4) = r;
        }
    }
}

extern "C" void kernel_launch(void* const* d_in, const int* in_sizes, int n_in,
                              void* d_out, int out_size)
{
    (void)in_sizes; (void)n_in; (void)out_size;
    const float* in0   = (const float*)d_in[0];
    const float* inL   = (const float*)d_in[1];
    const float* dw_w  = (const float*)d_in[2];
    const float* dw_b  = (const float*)d_in[3];
    const float* ln_g  = (const float*)d_in[4];
    const float* ln_b  = (const float*)d_in[5];
    const float* off_w = (const float*)d_in[6];
    const float* off_b = (const float*)d_in[7];
    float* out = (float*)d_out;

    prep_kernel<<<16, 1024>>>(off_w, dw_w);

    const int smem_bytes = SMEM_FLOATS * sizeof(float);   // 100608
    cudaFuncSetAttribute(das_fused_kernel,
                         cudaFuncAttributeMaxDynamicSharedMemorySize, smem_bytes);

    dim3 grid(2, H_, N_);
    das_fused_kernel<<<grid, 512, smem_bytes>>>(in0, inL, dw_b,
                                                ln_g, ln_b, off_b, out);
}